// round 13
// baseline (speedup 1.0000x reference)
#include <cuda_runtime.h>
#include <cuda_bf16.h>
#include <mma.h>
#include <math.h>
#include <stdint.h>

using namespace nvcuda;

// ---------------------------------------------------------------------------
// Problem constants
// ---------------------------------------------------------------------------
#define SEQ     2048
#define HID     2048
#define NHEADS  16
#define QLORA   1536
#define KVLORA  512
#define DROPE   64
#define DNOPE   128
#define DVDIM   128
#define QHD     192
#define QROW    (NHEADS*QHD)            // 3072
#define KVROW   (NHEADS*(DNOPE+DVDIM))  // 4096
#define CKVROW  (KVLORA+DROPE)          // 576
#define CATN    (QLORA + CKVROW)        // 2112 fused q/kv projection width
#define PERSIST_CTAS 296                // 148 SMs x 2 CTAs

// ---------------------------------------------------------------------------
// Scratch (device globals)
// ---------------------------------------------------------------------------
__device__ float g_qact[SEQ*CATN];
__device__ float g_qa  [SEQ*QLORA];
__device__ float g_q   [SEQ*QROW];
__device__ float g_kvn [SEQ*KVLORA];
__device__ float g_kpe [SEQ*DROPE];
__device__ float g_kv  [SEQ*KVROW];
__device__ float g_attn[SEQ*HID];
// tf32-rounded copies of GEMM inputs
__device__ float g_rx   [SEQ*HID];
__device__ float g_rwcat[HID*CATN];
__device__ float g_rwqb [QLORA*QROW];
__device__ float g_rwkvb[KVLORA*KVROW];
__device__ float g_rwo  [HID*HID];
// bf16 hi/lo pre-split attention operands
__device__ __nv_bfloat16 g_qhi [SEQ*QROW];
__device__ __nv_bfloat16 g_qlo [SEQ*QROW];
__device__ __nv_bfloat16 g_khi [SEQ*QROW];
__device__ __nv_bfloat16 g_klo [SEQ*QROW];
__device__ __nv_bfloat16 g_vthi[NHEADS*DVDIM*SEQ];
__device__ __nv_bfloat16 g_vtlo[NHEADS*DVDIM*SEQ];

__device__ __forceinline__ float rna(float x) {
    uint32_t r;
    asm("cvt.rna.tf32.f32 %0, %1;" : "=r"(r) : "f"(x));
    return __uint_as_float(r);
}

__device__ __forceinline__ void splitHL(float v, __nv_bfloat16& h, __nv_bfloat16& l) {
    h = __float2bfloat16(v);
    l = __float2bfloat16(v - __bfloat162float(h));
}

// ---------------------------------------------------------------------------
// elementwise tf32 round copy (float4)
// ---------------------------------------------------------------------------
__global__ __launch_bounds__(256) void round_copy_k(
    const float4* __restrict__ in, float4* __restrict__ out, int n4)
{
    int i = blockIdx.x * 256 + threadIdx.x;
    if (i < n4) {
        float4 v = in[i];
        v.x = rna(v.x); v.y = rna(v.y); v.z = rna(v.z); v.w = rna(v.w);
        out[i] = v;
    }
}

// strided round copy: W[K][N] -> out[k*outStride + off + n]
__global__ __launch_bounds__(256) void round_strided_k(
    const float* __restrict__ W, float* __restrict__ out,
    int N, int outStride, int off, int total)
{
    int idx = blockIdx.x * 256 + threadIdx.x;
    if (idx < total) {
        const int k = idx / N, n = idx % N;
        out[(size_t)k * outStride + off + n] = rna(W[idx]);
    }
}

// ---------------------------------------------------------------------------
// TF32 wmma GEMM, cp.async 3-stage ring, 2 CTAs/SM, PERSISTENT tile loop.
// C[M,N] = A[M,K]*B[K,N]. M%128==0, K%32==0 (>=3 chunks), N%4==0.
// ---------------------------------------------------------------------------
#define BM 128
#define BN 128
#define BK 32
#define AS_LD 36
#define BS_LD 132
#define STAGE_F (BM*AS_LD + BK*BS_LD)   // 8832 floats
#define NSTAGE 3
#define GEMM_SMEM (NSTAGE*STAGE_F*4)    // 105984 B

__global__ __launch_bounds__(256, 2) void tgemm_k(
    const float* __restrict__ A, const float* __restrict__ B,
    float* __restrict__ C, int M, int N, int K, int tilesX, int tiles)
{
    extern __shared__ float smem[];
    const int tid = threadIdx.x;
    const int warpId = tid >> 5;
    const int wr = warpId >> 2;
    const int wc = warpId & 3;
    const int nsteps = K / BK;

    for (int t = blockIdx.x; t < tiles; t += gridDim.x) {
        const int br = (t / tilesX) * BM;
        const int bc = (t % tilesX) * BN;

        wmma::fragment<wmma::accumulator, 16, 16, 8, float> acc[4][2];
#pragma unroll
        for (int i = 0; i < 4; i++)
#pragma unroll
            for (int j = 0; j < 2; j++)
                wmma::fill_fragment(acc[i][j], 0.f);

        auto issue = [&](int k0, int st) {
            float* As = smem + st * STAGE_F;
            float* Bs = As + BM * AS_LD;
#pragma unroll
            for (int i = 0; i < 4; i++) {
                const int lin = i * 256 + tid;
                const int r = lin >> 3, c = (lin & 7) << 2;
                uint32_t dst = (uint32_t)__cvta_generic_to_shared(&As[r*AS_LD + c]);
                const float* src = &A[(size_t)(br + r) * K + k0 + c];
                asm volatile("cp.async.cg.shared.global [%0], [%1], 16;\n"
                             :: "r"(dst), "l"(src));
            }
#pragma unroll
            for (int i = 0; i < 4; i++) {
                const int lin = i * 256 + tid;
                const int r = lin >> 5, c = (lin & 31) << 2;
                const int gc = bc + c;
                uint32_t dst = (uint32_t)__cvta_generic_to_shared(&Bs[r*BS_LD + c]);
                const float* src = &B[(size_t)(k0 + r) * N + gc];
                const int sz = (gc < N) ? 16 : 0;
                asm volatile("cp.async.cg.shared.global [%0], [%1], 16, %2;\n"
                             :: "r"(dst), "l"(src), "r"(sz));
            }
            asm volatile("cp.async.commit_group;\n");
        };

        issue(0, 0);
        if (nsteps > 1) issue(BK, 1);

        for (int s = 0; s < nsteps; s++) {
            asm volatile("cp.async.wait_group 1;\n");
            __syncthreads();
            if (s + 2 < nsteps) issue((s + 2) * BK, (s + 2) % NSTAGE);

            const float* As = smem + (s % NSTAGE) * STAGE_F;
            const float* Bs = As + BM * AS_LD;
#pragma unroll
            for (int kk = 0; kk < BK; kk += 8) {
                wmma::fragment<wmma::matrix_a, 16, 16, 8,
                               wmma::precision::tf32, wmma::row_major> af[4];
                wmma::fragment<wmma::matrix_b, 16, 16, 8,
                               wmma::precision::tf32, wmma::row_major> bf[2];
#pragma unroll
                for (int i = 0; i < 4; i++)
                    wmma::load_matrix_sync(af[i], &As[(wr*64 + i*16)*AS_LD + kk], AS_LD);
#pragma unroll
                for (int j = 0; j < 2; j++)
                    wmma::load_matrix_sync(bf[j], &Bs[kk*BS_LD + wc*32 + j*16], BS_LD);
#pragma unroll
                for (int i = 0; i < 4; i++)
#pragma unroll
                    for (int j = 0; j < 2; j++)
                        wmma::mma_sync(acc[i][j], af[i], bf[j], acc[i][j]);
            }
            __syncthreads();
        }
        // drain remaining outstanding group before next tile reuses stage 0/1
        asm volatile("cp.async.wait_group 0;\n");

#pragma unroll
        for (int i = 0; i < 4; i++) {
            const int gr = br + wr*64 + i*16;
#pragma unroll
            for (int j = 0; j < 2; j++) {
                const int gc = bc + wc*32 + j*16;
                if (gc < N)
                    wmma::store_matrix_sync(&C[(size_t)gr * N + gc], acc[i][j],
                                            N, wmma::mem_row_major);
            }
        }
        __syncthreads();
    }
}

// ---------------------------------------------------------------------------
// RMSNorm (output tf32-rounded: feeds a GEMM)
// ---------------------------------------------------------------------------
__global__ __launch_bounds__(256) void rmsnorm_k(
    const float* __restrict__ in, int istride,
    float* __restrict__ out, int ostride,
    int dim, const float* __restrict__ w)
{
    const int row = blockIdx.x;
    const float* x = in + (size_t)row * istride;
    float* y = out + (size_t)row * ostride;

    float ss = 0.f;
    for (int i = threadIdx.x; i < dim; i += blockDim.x) {
        float v = x[i];
        ss = fmaf(v, v, ss);
    }
#pragma unroll
    for (int o = 16; o; o >>= 1) ss += __shfl_xor_sync(0xffffffffu, ss, o);

    __shared__ float red[8];
    if ((threadIdx.x & 31) == 0) red[threadIdx.x >> 5] = ss;
    __syncthreads();
    __shared__ float s_rstd;
    if (threadIdx.x == 0) {
        float v = 0.f;
        for (int i = 0; i < 8; i++) v += red[i];
        s_rstd = rsqrtf(v / (float)dim + 1e-6f);
    }
    __syncthreads();
    const float rstd = s_rstd;
    for (int i = threadIdx.x; i < dim; i += blockDim.x)
        y[i] = rna(x[i] * rstd * w[i]);
}

// ---------------------------------------------------------------------------
// RoPE kernels
// ---------------------------------------------------------------------------
__global__ __launch_bounds__(512) void rope_q_k(float* __restrict__ q)
{
    const int t = blockIdx.x;
    const int h = threadIdx.x >> 5;
    const int i = threadIdx.x & 31;
    const float inv = powf(10000.f, -(float)i / 32.f);
    float s, c;
    sincosf((float)t * inv, &s, &c);
    float* base = q + (size_t)t * QROW + h * QHD + DNOPE;
    const float x1 = base[i];
    const float x2 = base[i + 32];
    base[i]      = x1 * c - x2 * s;
    base[i + 32] = x2 * c + x1 * s;
}

__global__ __launch_bounds__(32) void rope_k_k(
    const float* __restrict__ qact, float* __restrict__ kpe)
{
    const int t = blockIdx.x;
    const int i = threadIdx.x;
    const float inv = powf(10000.f, -(float)i / 32.f);
    float s, c;
    sincosf((float)t * inv, &s, &c);
    const float x1 = qact[(size_t)t * CATN + QLORA + KVLORA + i];
    const float x2 = qact[(size_t)t * CATN + QLORA + KVLORA + 32 + i];
    kpe[(size_t)t * DROPE + i]      = x1 * c - x2 * s;
    kpe[(size_t)t * DROPE + 32 + i] = x2 * c + x1 * s;
}

// ---------------------------------------------------------------------------
// bf16 hi/lo split prep kernels
// ---------------------------------------------------------------------------
__global__ __launch_bounds__(256) void split_q_k(
    const float* __restrict__ q,
    __nv_bfloat16* __restrict__ qhi, __nv_bfloat16* __restrict__ qlo)
{
    const int idx = blockIdx.x * 256 + threadIdx.x;
    const float scale = rsqrtf(192.f);
    const float v = q[idx] * scale;
    __nv_bfloat16 h, l;
    splitHL(v, h, l);
    qhi[idx] = h; qlo[idx] = l;
}

__global__ __launch_bounds__(256) void split_k_k(
    const float* __restrict__ kv, const float* __restrict__ kpe,
    __nv_bfloat16* __restrict__ khi, __nv_bfloat16* __restrict__ klo)
{
    const int idx = blockIdx.x * 256 + threadIdx.x;
    const int t = idx / QROW;
    const int j = idx % QROW;
    const int h = j / QHD;
    const int d = j % QHD;
    const float v = (d < DNOPE)
        ? kv[(size_t)t * KVROW + h * 256 + d]
        : kpe[(size_t)t * DROPE + (d - DNOPE)];
    __nv_bfloat16 hi, lo;
    splitHL(v, hi, lo);
    khi[idx] = hi; klo[idx] = lo;
}

__global__ __launch_bounds__(256) void split_vt_k(
    const float* __restrict__ kv,
    __nv_bfloat16* __restrict__ vthi, __nv_bfloat16* __restrict__ vtlo)
{
    __shared__ float tile[64][65];
    const int tb = blockIdx.x;
    const int nb = blockIdx.y;
    const int h  = blockIdx.z;
    const int tid = threadIdx.x;
#pragma unroll
    for (int i = 0; i < 16; i++) {
        const int lin = i * 256 + tid;
        const int t = lin >> 6, n = lin & 63;
        tile[t][n] = kv[(size_t)(tb*64 + t) * KVROW + h*256 + DNOPE + nb*64 + n];
    }
    __syncthreads();
#pragma unroll
    for (int i = 0; i < 16; i++) {
        const int lin = i * 256 + tid;
        const int n = lin >> 6, t = lin & 63;
        __nv_bfloat16 hi, lo;
        splitHL(tile[t][n], hi, lo);
        const size_t dst = (size_t)(h*DVDIM + nb*64 + n) * SEQ + tb*64 + t;
        vthi[dst] = hi; vtlo[dst] = lo;
    }
}

// ---------------------------------------------------------------------------
// Tensor-core flash attention (unchanged from R12).
// ---------------------------------------------------------------------------
#define QPS 200
#define KPS 72
#define VPS 72
#define PPS 72

#define OB_QHI 0
#define OB_QLO (OB_QHI + 64*QPS*2)
#define OB_KHI (OB_QLO + 64*QPS*2)
#define OB_KLO (OB_KHI + 64*KPS*2)
#define OB_VHI (OB_KLO + 64*KPS*2)
#define OB_VLO (OB_VHI + 64*VPS*2)
#define OB_PHI (OB_VLO + 64*VPS*2)
#define OB_PLO (OB_PHI + 64*PPS*2)
#define OB_ST  (OB_PLO + 64*PPS*2)
#define ATTN_SMEM (OB_ST + 704*4)

__device__ __forceinline__ void mma16(float* d,
    uint32_t a0, uint32_t a1, uint32_t a2, uint32_t a3,
    uint32_t b0, uint32_t b1)
{
    asm volatile(
        "mma.sync.aligned.m16n8k16.row.col.f32.bf16.bf16.f32 "
        "{%0,%1,%2,%3}, {%4,%5,%6,%7}, {%8,%9}, {%0,%1,%2,%3};\n"
        : "+f"(d[0]), "+f"(d[1]), "+f"(d[2]), "+f"(d[3])
        : "r"(a0), "r"(a1), "r"(a2), "r"(a3), "r"(b0), "r"(b1));
}

__device__ __forceinline__ void ldm4(uint32_t* r, uint32_t a) {
    asm volatile("ldmatrix.sync.aligned.m8n8.x4.shared.b16 {%0,%1,%2,%3}, [%4];"
        : "=r"(r[0]), "=r"(r[1]), "=r"(r[2]), "=r"(r[3]) : "r"(a));
}
__device__ __forceinline__ void ldm2(uint32_t* r, uint32_t a) {
    asm volatile("ldmatrix.sync.aligned.m8n8.x2.shared.b16 {%0,%1}, [%2];"
        : "=r"(r[0]), "=r"(r[1]) : "r"(a));
}
__device__ __forceinline__ void cp16(uint32_t dst, const void* src) {
    asm volatile("cp.async.cg.shared.global [%0], [%1], 16;\n"
                 :: "r"(dst), "l"(src));
}

__global__ __launch_bounds__(256, 2) void mla_attn_tc(
    const __nv_bfloat16* __restrict__ qhi, const __nv_bfloat16* __restrict__ qlo,
    const __nv_bfloat16* __restrict__ khi, const __nv_bfloat16* __restrict__ klo,
    const __nv_bfloat16* __restrict__ vthi, const __nv_bfloat16* __restrict__ vtlo,
    float* __restrict__ out)
{
    extern __shared__ char smraw[];
    __nv_bfloat16* Qh = (__nv_bfloat16*)(smraw + OB_QHI);
    __nv_bfloat16* Ql = (__nv_bfloat16*)(smraw + OB_QLO);
    __nv_bfloat16* Kh = (__nv_bfloat16*)(smraw + OB_KHI);
    __nv_bfloat16* Kl = (__nv_bfloat16*)(smraw + OB_KLO);
    __nv_bfloat16* Vh = (__nv_bfloat16*)(smraw + OB_VHI);
    __nv_bfloat16* Vl = (__nv_bfloat16*)(smraw + OB_VLO);
    __nv_bfloat16* Ph = (__nv_bfloat16*)(smraw + OB_PHI);
    __nv_bfloat16* Pl = (__nv_bfloat16*)(smraw + OB_PLO);
    float* smM  = (float*)(smraw + OB_ST);
    float* smL  = smM + 64;
    float* smF  = smL + 64;
    float* redM = smF + 64;
    float* redS = redM + 256;

    const int h  = blockIdx.y;
    const int qb = gridDim.x - 1 - blockIdx.x;
    const int tid = threadIdx.x;
    const int lane = tid & 31;
    const int wid = tid >> 5;
    const int wr = wid >> 2;
    const int wc = wid & 3;
    const int lq = lane >> 2;
    const int lr = lane & 3;

    const int arow = lane & 15;
    const int acol8 = (lane >> 4) * 8;
    const int brow = lane & 7;
    const int bcol8 = ((lane >> 3) & 1) * 8;

#pragma unroll
    for (int i = 0; i < 6; i++) {
        const int lin = i * 256 + tid;
        const int r = lin / 24, s = lin % 24;
        const size_t g = (size_t)(qb*64 + r) * QROW + h*QHD + s*8;
        cp16((uint32_t)__cvta_generic_to_shared(&Qh[r*QPS + s*8]), &qhi[g]);
        cp16((uint32_t)__cvta_generic_to_shared(&Ql[r*QPS + s*8]), &qlo[g]);
    }
    asm volatile("cp.async.commit_group;\n");
    if (tid < 64) { smM[tid] = -INFINITY; smL[tid] = 0.f; }

    float Oacc[2][4][4];
#pragma unroll
    for (int mt = 0; mt < 2; mt++)
#pragma unroll
        for (int nt = 0; nt < 4; nt++)
#pragma unroll
            for (int i = 0; i < 4; i++) Oacc[mt][nt][i] = 0.f;

    for (int kb = 0; kb <= qb; kb++) {
        float Sacc[2][2][4];
#pragma unroll
        for (int mt = 0; mt < 2; mt++)
#pragma unroll
            for (int nt = 0; nt < 2; nt++)
#pragma unroll
                for (int i = 0; i < 4; i++) Sacc[mt][nt][i] = 0.f;

#pragma unroll 1
        for (int c = 0; c < 3; c++) {
            if (c) __syncthreads();
#pragma unroll
            for (int i = 0; i < 2; i++) {
                const int lin = i * 256 + tid;
                const int r = lin >> 3, s = lin & 7;
                const size_t g = (size_t)(kb*64 + r) * QROW + h*QHD + c*64 + s*8;
                cp16((uint32_t)__cvta_generic_to_shared(&Kh[r*KPS + s*8]), &khi[g]);
                cp16((uint32_t)__cvta_generic_to_shared(&Kl[r*KPS + s*8]), &klo[g]);
            }
            asm volatile("cp.async.commit_group;\n");
            asm volatile("cp.async.wait_group 0;\n");
            __syncthreads();

#pragma unroll
            for (int ks = 0; ks < 4; ks++) {
                const int kof = ks * 16;
                uint32_t bh[2][2], bl[2][2];
#pragma unroll
                for (int nt = 0; nt < 2; nt++) {
                    const int n = wc*16 + nt*8 + brow;
                    ldm2(bh[nt], (uint32_t)__cvta_generic_to_shared(
                        &Kh[n*KPS + kof + bcol8]));
                    ldm2(bl[nt], (uint32_t)__cvta_generic_to_shared(
                        &Kl[n*KPS + kof + bcol8]));
                }
#pragma unroll
                for (int mt = 0; mt < 2; mt++) {
                    const int r = wr*32 + mt*16 + arow;
                    uint32_t ah[4], al[4];
                    ldm4(ah, (uint32_t)__cvta_generic_to_shared(
                        &Qh[r*QPS + c*64 + kof + acol8]));
                    ldm4(al, (uint32_t)__cvta_generic_to_shared(
                        &Ql[r*QPS + c*64 + kof + acol8]));
#pragma unroll
                    for (int nt = 0; nt < 2; nt++) {
                        mma16(Sacc[mt][nt], ah[0], ah[1], ah[2], ah[3], bh[nt][0], bh[nt][1]);
                        mma16(Sacc[mt][nt], al[0], al[1], al[2], al[3], bh[nt][0], bh[nt][1]);
                        mma16(Sacc[mt][nt], ah[0], ah[1], ah[2], ah[3], bl[nt][0], bl[nt][1]);
                    }
                }
            }
        }

        float tmax[2][2] = { {-INFINITY,-INFINITY}, {-INFINITY,-INFINITY} };
#pragma unroll
        for (int mt = 0; mt < 2; mt++)
#pragma unroll
            for (int nt = 0; nt < 2; nt++)
#pragma unroll
                for (int i = 0; i < 4; i++) {
                    if (kb == qb) {
                        const int row = wr*32 + mt*16 + lq + (i >> 1)*8;
                        const int col = wc*16 + nt*8 + lr*2 + (i & 1);
                        if (col > row) Sacc[mt][nt][i] = -INFINITY;
                    }
                    tmax[mt][i>>1] = fmaxf(tmax[mt][i>>1], Sacc[mt][nt][i]);
                }
#pragma unroll
        for (int mt = 0; mt < 2; mt++)
#pragma unroll
            for (int u = 0; u < 2; u++) {
                float v = tmax[mt][u];
                v = fmaxf(v, __shfl_xor_sync(0xffffffffu, v, 1));
                v = fmaxf(v, __shfl_xor_sync(0xffffffffu, v, 2));
                tmax[mt][u] = v;
            }
        if (lr == 0) {
#pragma unroll
            for (int mt = 0; mt < 2; mt++)
#pragma unroll
                for (int u = 0; u < 2; u++)
                    redM[(wr*32 + mt*16 + lq + u*8)*4 + wc] = tmax[mt][u];
        }
        __syncthreads();

        if (wc == 0 && lr == 0) {
#pragma unroll
            for (int mt = 0; mt < 2; mt++)
#pragma unroll
                for (int u = 0; u < 2; u++) {
                    const int row = wr*32 + mt*16 + lq + u*8;
                    float mx = fmaxf(fmaxf(redM[row*4+0], redM[row*4+1]),
                                     fmaxf(redM[row*4+2], redM[row*4+3]));
                    const float mo = smM[row];
                    const float mn = fmaxf(mo, mx);
                    smM[row] = mn;
                    smF[row] = __expf(mo - mn);
                }
        }
        __syncthreads();

        float mn[2][2];
#pragma unroll
        for (int mt = 0; mt < 2; mt++)
#pragma unroll
            for (int u = 0; u < 2; u++)
                mn[mt][u] = smM[wr*32 + mt*16 + lq + u*8];

        float tsum[2][2] = { {0.f,0.f}, {0.f,0.f} };
#pragma unroll
        for (int mt = 0; mt < 2; mt++)
#pragma unroll
            for (int nt = 0; nt < 2; nt++)
#pragma unroll
                for (int u = 0; u < 2; u++) {
                    const float p0 = __expf(Sacc[mt][nt][u*2+0] - mn[mt][u]);
                    const float p1 = __expf(Sacc[mt][nt][u*2+1] - mn[mt][u]);
                    const int row = wr*32 + mt*16 + lq + u*8;
                    const int col = wc*16 + nt*8 + lr*2;
                    __nv_bfloat16 h0, l0, h1, l1;
                    splitHL(p0, h0, l0);
                    splitHL(p1, h1, l1);
                    *(uint32_t*)&Ph[row*PPS + col] =
                        (uint32_t)__bfloat16_as_ushort(h0)
                      | ((uint32_t)__bfloat16_as_ushort(h1) << 16);
                    *(uint32_t*)&Pl[row*PPS + col] =
                        (uint32_t)__bfloat16_as_ushort(l0)
                      | ((uint32_t)__bfloat16_as_ushort(l1) << 16);
                    tsum[mt][u] += p0 + p1;
                }
#pragma unroll
        for (int mt = 0; mt < 2; mt++)
#pragma unroll
            for (int u = 0; u < 2; u++) {
                float v = tsum[mt][u];
                v += __shfl_xor_sync(0xffffffffu, v, 1);
                v += __shfl_xor_sync(0xffffffffu, v, 2);
                tsum[mt][u] = v;
            }
        if (lr == 0) {
#pragma unroll
            for (int mt = 0; mt < 2; mt++)
#pragma unroll
                for (int u = 0; u < 2; u++)
                    redS[(wr*32 + mt*16 + lq + u*8)*4 + wc] = tsum[mt][u];
        }
#pragma unroll
        for (int mt = 0; mt < 2; mt++) {
            const int r0 = wr*32 + mt*16 + lq;
            const float f0 = smF[r0], f1 = smF[r0 + 8];
#pragma unroll
            for (int nt = 0; nt < 4; nt++) {
                Oacc[mt][nt][0] *= f0; Oacc[mt][nt][1] *= f0;
                Oacc[mt][nt][2] *= f1; Oacc[mt][nt][3] *= f1;
            }
        }
        __syncthreads();

        if (wc == 0 && lr == 0) {
#pragma unroll
            for (int mt = 0; mt < 2; mt++)
#pragma unroll
                for (int u = 0; u < 2; u++) {
                    const int row = wr*32 + mt*16 + lq + u*8;
                    smL[row] = smL[row]*smF[row] +
                        (redS[row*4+0] + redS[row*4+1] + redS[row*4+2] + redS[row*4+3]);
                }
        }

#pragma unroll 1
        for (int c = 0; c < 2; c++) {
            __syncthreads();
#pragma unroll
            for (int i = 0; i < 2; i++) {
                const int lin = i * 256 + tid;
                const int n = lin >> 3, s = lin & 7;
                const size_t g = (size_t)(h*DVDIM + c*64 + n) * SEQ + kb*64 + s*8;
                cp16((uint32_t)__cvta_generic_to_shared(&Vh[n*VPS + s*8]), &vthi[g]);
                cp16((uint32_t)__cvta_generic_to_shared(&Vl[n*VPS + s*8]), &vtlo[g]);
            }
            asm volatile("cp.async.commit_group;\n");
            asm volatile("cp.async.wait_group 0;\n");
            __syncthreads();

#pragma unroll
            for (int ks = 0; ks < 4; ks++) {
                const int kof = ks * 16;
                uint32_t bh[2][2], bl[2][2];
#pragma unroll
                for (int ntl = 0; ntl < 2; ntl++) {
                    const int n = ntl*32 + wc*8 + brow;
                    ldm2(bh[ntl], (uint32_t)__cvta_generic_to_shared(
                        &Vh[n*VPS + kof + bcol8]));
                    ldm2(bl[ntl], (uint32_t)__cvta_generic_to_shared(
                        &Vl[n*VPS + kof + bcol8]));
                }
#pragma unroll
                for (int mt = 0; mt < 2; mt++) {
                    const int r = wr*32 + mt*16 + arow;
                    uint32_t ah[4], al[4];
                    ldm4(ah, (uint32_t)__cvta_generic_to_shared(
                        &Ph[r*PPS + kof + acol8]));
                    ldm4(al, (uint32_t)__cvta_generic_to_shared(
                        &Pl[r*PPS + kof + acol8]));
#pragma unroll
                    for (int ntl = 0; ntl < 2; ntl++) {
                        const int nt = c*2 + ntl;
                        mma16(Oacc[mt][nt], ah[0], ah[1], ah[2], ah[3], bh[ntl][0], bh[ntl][1]);
                        mma16(Oacc[mt][nt], al[0], al[1], al[2], al[3], bh[ntl][0], bh[ntl][1]);
                        mma16(Oacc[mt][nt], ah[0], ah[1], ah[2], ah[3], bl[ntl][0], bl[ntl][1]);
                    }
                }
            }
        }
    }

    __syncthreads();

#pragma unroll
    for (int mt = 0; mt < 2; mt++) {
        const int r0 = wr*32 + mt*16 + lq;
        const float inv0 = 1.f / smL[r0];
        const float inv1 = 1.f / smL[r0 + 8];
#pragma unroll
        for (int nt = 0; nt < 4; nt++) {
#pragma unroll
            for (int i = 0; i < 4; i++) {
                const int row = (i < 2) ? r0 : (r0 + 8);
                const int col = nt*32 + wc*8 + lr*2 + (i & 1);
                out[(size_t)(qb*64 + row) * HID + h*DVDIM + col] =
                    rna(Oacc[mt][nt][i] * ((i < 2) ? inv0 : inv1));
            }
        }
    }
}

// ---------------------------------------------------------------------------
// Launch
// ---------------------------------------------------------------------------
static inline void launch_tgemm(const float* A, const float* B, float* C,
                                int M, int N, int K)
{
    const int tilesX = (N + BN - 1) / BN;
    const int tiles = tilesX * (M / BM);
    const int grid = tiles < PERSIST_CTAS ? tiles : PERSIST_CTAS;
    tgemm_k<<<grid, 256, GEMM_SMEM>>>(A, B, C, M, N, K, tilesX, tiles);
}

static inline void launch_round(const float* in, float* out, int n)
{
    const int n4 = n / 4;
    round_copy_k<<<(n4 + 255) / 256, 256>>>(
        (const float4*)in, (float4*)out, n4);
}

extern "C" void kernel_launch(void* const* d_in, const int* in_sizes, int n_in,
                              void* d_out, int out_size)
{
    const float* x        = (const float*)d_in[0];
    const float* wq_a     = (const float*)d_in[1];
    const float* q_a_ln_w = (const float*)d_in[2];
    const float* wq_b     = (const float*)d_in[3];
    const float* wkv_a    = (const float*)d_in[4];
    const float* kv_a_ln_w= (const float*)d_in[5];
    const float* wkv_b    = (const float*)d_in[6];
    const float* wo       = (const float*)d_in[7];
    float* out            = (float*)d_out;

    float *qact, *qa, *qbuf, *kvn, *kpe, *kv, *attn;
    float *rx, *rwcat, *rwqb, *rwkvb, *rwo;
    __nv_bfloat16 *qhi, *qlo, *khi, *klo, *vthi, *vtlo;
    cudaGetSymbolAddress((void**)&qact,  g_qact);
    cudaGetSymbolAddress((void**)&qa,    g_qa);
    cudaGetSymbolAddress((void**)&qbuf,  g_q);
    cudaGetSymbolAddress((void**)&kvn,   g_kvn);
    cudaGetSymbolAddress((void**)&kpe,   g_kpe);
    cudaGetSymbolAddress((void**)&kv,    g_kv);
    cudaGetSymbolAddress((void**)&attn,  g_attn);
    cudaGetSymbolAddress((void**)&rx,    g_rx);
    cudaGetSymbolAddress((void**)&rwcat, g_rwcat);
    cudaGetSymbolAddress((void**)&rwqb,  g_rwqb);
    cudaGetSymbolAddress((void**)&rwkvb, g_rwkvb);
    cudaGetSymbolAddress((void**)&rwo,   g_rwo);
    cudaGetSymbolAddress((void**)&qhi,   g_qhi);
    cudaGetSymbolAddress((void**)&qlo,   g_qlo);
    cudaGetSymbolAddress((void**)&khi,   g_khi);
    cudaGetSymbolAddress((void**)&klo,   g_klo);
    cudaGetSymbolAddress((void**)&vthi,  g_vthi);
    cudaGetSymbolAddress((void**)&vtlo,  g_vtlo);

    cudaFuncSetAttribute(tgemm_k,
        cudaFuncAttributeMaxDynamicSharedMemorySize, GEMM_SMEM);
    cudaFuncSetAttribute(mla_attn_tc,
        cudaFuncAttributeMaxDynamicSharedMemorySize, ATTN_SMEM);

    // idx 0..2 preps; idx 3 = profiled fused GEMM (M=2048, N=2112, K=2048)
    launch_round(x, rx, SEQ*HID);                                        // 0
    round_strided_k<<<HID*QLORA/256, 256>>>(
        wq_a, rwcat, QLORA, CATN, 0, HID*QLORA);                         // 1
    round_strided_k<<<(HID*CKVROW + 255)/256, 256>>>(
        wkv_a, rwcat, CKVROW, CATN, QLORA, HID*CKVROW);                  // 2
    launch_tgemm(rx, rwcat, qact, SEQ, CATN, HID);                       // 3 <- profiled

    // q path
    rmsnorm_k<<<SEQ, 256>>>(qact, CATN, qa, QLORA, QLORA, q_a_ln_w);
    launch_round(wq_b, rwqb, QLORA*QROW);
    launch_tgemm(qa, rwqb, qbuf, SEQ, QROW, QLORA);

    // kv path
    rmsnorm_k<<<SEQ, 256>>>(qact + QLORA, CATN, kvn, KVLORA, KVLORA, kv_a_ln_w);
    rope_k_k<<<SEQ, 32>>>(qact, kpe);
    launch_round(wkv_b, rwkvb, KVLORA*KVROW);
    launch_tgemm(kvn, rwkvb, kv, SEQ, KVROW, KVLORA);

    // rope q, then bf16 hi/lo pre-splits
    rope_q_k<<<SEQ, 512>>>(qbuf);
    split_q_k<<<SEQ*QROW/256, 256>>>(qbuf, qhi, qlo);
    split_k_k<<<SEQ*QROW/256, 256>>>(kv, kpe, khi, klo);
    {
        dim3 g(SEQ/64, DVDIM/64, NHEADS);
        split_vt_k<<<g, 256>>>(kv, vthi, vtlo);
    }

    // attention (writes tf32-rounded output)
    dim3 agrid(SEQ / 64, NHEADS);
    mla_attn_tc<<<agrid, 256, ATTN_SMEM>>>(qhi, qlo, khi, klo, vthi, vtlo, attn);

    // output projection
    launch_round(wo, rwo, HID*HID);
    launch_tgemm(attn, rwo, out, SEQ, HID, NHEADS * DVDIM);
}

// round 16
// speedup vs baseline: 1.0202x; 1.0202x over previous
#include <cuda_runtime.h>
#include <cuda_bf16.h>
#include <mma.h>
#include <math.h>
#include <stdint.h>

using namespace nvcuda;

// ---------------------------------------------------------------------------
// Problem constants
// ---------------------------------------------------------------------------
#define SEQ     2048
#define HID     2048
#define NHEADS  16
#define QLORA   1536
#define KVLORA  512
#define DROPE   64
#define DNOPE   128
#define DVDIM   128
#define QHD     192
#define QROW    (NHEADS*QHD)            // 3072
#define KVROW   (NHEADS*(DNOPE+DVDIM))  // 4096
#define CKVROW  (KVLORA+DROPE)          // 576
#define CATN    (QLORA + CKVROW)        // 2112
#define PERSIST_CTAS 296

// ---------------------------------------------------------------------------
// Scratch (device globals)
// ---------------------------------------------------------------------------
__device__ float g_qact[SEQ*CATN];
__device__ float g_qa  [SEQ*QLORA];
__device__ float g_q   [SEQ*QROW];
__device__ float g_kvn [SEQ*KVLORA];
__device__ float g_kpe [SEQ*DROPE];
__device__ float g_kv  [SEQ*KVROW];
__device__ float g_attn[SEQ*HID];
// tf32-rounded copies of GEMM inputs
__device__ float g_rx   [SEQ*HID];
__device__ float g_rwcat[HID*CATN];
__device__ float g_rwqb [QLORA*QROW];
__device__ float g_rwkvb[KVLORA*KVROW];
__device__ float g_rwo  [HID*HID];
// bf16 hi/lo pre-split attention operands
__device__ __nv_bfloat16 g_qhi [SEQ*QROW];
__device__ __nv_bfloat16 g_qlo [SEQ*QROW];
__device__ __nv_bfloat16 g_khi [SEQ*QROW];
__device__ __nv_bfloat16 g_klo [SEQ*QROW];
__device__ __nv_bfloat16 g_vthi[NHEADS*DVDIM*SEQ];
__device__ __nv_bfloat16 g_vtlo[NHEADS*DVDIM*SEQ];

__device__ __forceinline__ float rna(float x) {
    uint32_t r;
    asm("cvt.rna.tf32.f32 %0, %1;" : "=r"(r) : "f"(x));
    return __uint_as_float(r);
}

__device__ __forceinline__ void splitHL(float v, __nv_bfloat16& h, __nv_bfloat16& l) {
    h = __float2bfloat16(v);
    l = __float2bfloat16(v - __bfloat162float(h));
}

// ---------------------------------------------------------------------------
// elementwise tf32 round copy (float4)
// ---------------------------------------------------------------------------
__global__ __launch_bounds__(256) void round_copy_k(
    const float4* __restrict__ in, float4* __restrict__ out, int n4)
{
    int i = blockIdx.x * 256 + threadIdx.x;
    if (i < n4) {
        float4 v = in[i];
        v.x = rna(v.x); v.y = rna(v.y); v.z = rna(v.z); v.w = rna(v.w);
        out[i] = v;
    }
}

__global__ __launch_bounds__(256) void round_strided_k(
    const float* __restrict__ W, float* __restrict__ out,
    int N, int outStride, int off, int total)
{
    int idx = blockIdx.x * 256 + threadIdx.x;
    if (idx < total) {
        const int k = idx / N, n = idx % N;
        out[(size_t)k * outStride + off + n] = rna(W[idx]);
    }
}

// ---------------------------------------------------------------------------
// TF32 wmma GEMM, cp.async 3-stage ring, 2 CTAs/SM, persistent tiles.
// One barrier per chunk (bottom sync removed; 3-stage ring makes it safe).
// ---------------------------------------------------------------------------
#define BM 128
#define BN 128
#define BK 32
#define AS_LD 36
#define BS_LD 132
#define STAGE_F (BM*AS_LD + BK*BS_LD)
#define NSTAGE 3
#define GEMM_SMEM (NSTAGE*STAGE_F*4)

__global__ __launch_bounds__(256, 2) void tgemm_k(
    const float* __restrict__ A, const float* __restrict__ B,
    float* __restrict__ C, int M, int N, int K, int tilesX, int tiles)
{
    extern __shared__ float smem[];
    const int tid = threadIdx.x;
    const int warpId = tid >> 5;
    const int wr = warpId >> 2;
    const int wc = warpId & 3;
    const int nsteps = K / BK;

    for (int t = blockIdx.x; t < tiles; t += gridDim.x) {
        const int br = (t / tilesX) * BM;
        const int bc = (t % tilesX) * BN;

        wmma::fragment<wmma::accumulator, 16, 16, 8, float> acc[4][2];
#pragma unroll
        for (int i = 0; i < 4; i++)
#pragma unroll
            for (int j = 0; j < 2; j++)
                wmma::fill_fragment(acc[i][j], 0.f);

        auto issue = [&](int k0, int st) {
            float* As = smem + st * STAGE_F;
            float* Bs = As + BM * AS_LD;
#pragma unroll
            for (int i = 0; i < 4; i++) {
                const int lin = i * 256 + tid;
                const int r = lin >> 3, c = (lin & 7) << 2;
                uint32_t dst = (uint32_t)__cvta_generic_to_shared(&As[r*AS_LD + c]);
                const float* src = &A[(size_t)(br + r) * K + k0 + c];
                asm volatile("cp.async.cg.shared.global [%0], [%1], 16;\n"
                             :: "r"(dst), "l"(src));
            }
#pragma unroll
            for (int i = 0; i < 4; i++) {
                const int lin = i * 256 + tid;
                const int r = lin >> 5, c = (lin & 31) << 2;
                const int gc = bc + c;
                uint32_t dst = (uint32_t)__cvta_generic_to_shared(&Bs[r*BS_LD + c]);
                const float* src = &B[(size_t)(k0 + r) * N + gc];
                const int sz = (gc < N) ? 16 : 0;
                asm volatile("cp.async.cg.shared.global [%0], [%1], 16, %2;\n"
                             :: "r"(dst), "l"(src), "r"(sz));
            }
            asm volatile("cp.async.commit_group;\n");
        };

        issue(0, 0);
        if (nsteps > 1) issue(BK, 1);

        for (int s = 0; s < nsteps; s++) {
            asm volatile("cp.async.wait_group 1;\n");
            __syncthreads();
            if (s + 2 < nsteps) issue((s + 2) * BK, (s + 2) % NSTAGE);

            const float* As = smem + (s % NSTAGE) * STAGE_F;
            const float* Bs = As + BM * AS_LD;
#pragma unroll
            for (int kk = 0; kk < BK; kk += 8) {
                wmma::fragment<wmma::matrix_a, 16, 16, 8,
                               wmma::precision::tf32, wmma::row_major> af[4];
                wmma::fragment<wmma::matrix_b, 16, 16, 8,
                               wmma::precision::tf32, wmma::row_major> bf[2];
#pragma unroll
                for (int i = 0; i < 4; i++)
                    wmma::load_matrix_sync(af[i], &As[(wr*64 + i*16)*AS_LD + kk], AS_LD);
#pragma unroll
                for (int j = 0; j < 2; j++)
                    wmma::load_matrix_sync(bf[j], &Bs[kk*BS_LD + wc*32 + j*16], BS_LD);
#pragma unroll
                for (int i = 0; i < 4; i++)
#pragma unroll
                    for (int j = 0; j < 2; j++)
                        wmma::mma_sync(acc[i][j], af[i], bf[j], acc[i][j]);
            }
            // no bottom barrier: issue() writes stage (s+2)%3, disjoint from
            // the stage being read (s%3) and the waited stage ((s+1)%3).
        }
        asm volatile("cp.async.wait_group 0;\n");

#pragma unroll
        for (int i = 0; i < 4; i++) {
            const int gr = br + wr*64 + i*16;
#pragma unroll
            for (int j = 0; j < 2; j++) {
                const int gc = bc + wc*32 + j*16;
                if (gc < N)
                    wmma::store_matrix_sync(&C[(size_t)gr * N + gc], acc[i][j],
                                            N, wmma::mem_row_major);
            }
        }
        __syncthreads();   // tile boundary: protects stage reuse next tile
    }
}

// ---------------------------------------------------------------------------
// RMSNorm
// ---------------------------------------------------------------------------
__global__ __launch_bounds__(256) void rmsnorm_k(
    const float* __restrict__ in, int istride,
    float* __restrict__ out, int ostride,
    int dim, const float* __restrict__ w)
{
    const int row = blockIdx.x;
    const float* x = in + (size_t)row * istride;
    float* y = out + (size_t)row * ostride;

    float ss = 0.f;
    for (int i = threadIdx.x; i < dim; i += blockDim.x) {
        float v = x[i];
        ss = fmaf(v, v, ss);
    }
#pragma unroll
    for (int o = 16; o; o >>= 1) ss += __shfl_xor_sync(0xffffffffu, ss, o);

    __shared__ float red[8];
    if ((threadIdx.x & 31) == 0) red[threadIdx.x >> 5] = ss;
    __syncthreads();
    __shared__ float s_rstd;
    if (threadIdx.x == 0) {
        float v = 0.f;
        for (int i = 0; i < 8; i++) v += red[i];
        s_rstd = rsqrtf(v / (float)dim + 1e-6f);
    }
    __syncthreads();
    const float rstd = s_rstd;
    for (int i = threadIdx.x; i < dim; i += blockDim.x)
        y[i] = rna(x[i] * rstd * w[i]);
}

// ---------------------------------------------------------------------------
// RoPE kernels
// ---------------------------------------------------------------------------
__global__ __launch_bounds__(512) void rope_q_k(float* __restrict__ q)
{
    const int t = blockIdx.x;
    const int h = threadIdx.x >> 5;
    const int i = threadIdx.x & 31;
    const float inv = powf(10000.f, -(float)i / 32.f);
    float s, c;
    sincosf((float)t * inv, &s, &c);
    float* base = q + (size_t)t * QROW + h * QHD + DNOPE;
    const float x1 = base[i];
    const float x2 = base[i + 32];
    base[i]      = x1 * c - x2 * s;
    base[i + 32] = x2 * c + x1 * s;
}

__global__ __launch_bounds__(32) void rope_k_k(
    const float* __restrict__ qact, float* __restrict__ kpe)
{
    const int t = blockIdx.x;
    const int i = threadIdx.x;
    const float inv = powf(10000.f, -(float)i / 32.f);
    float s, c;
    sincosf((float)t * inv, &s, &c);
    const float x1 = qact[(size_t)t * CATN + QLORA + KVLORA + i];
    const float x2 = qact[(size_t)t * CATN + QLORA + KVLORA + 32 + i];
    kpe[(size_t)t * DROPE + i]      = x1 * c - x2 * s;
    kpe[(size_t)t * DROPE + 32 + i] = x2 * c + x1 * s;
}

// ---------------------------------------------------------------------------
// bf16 hi/lo split prep kernels
// ---------------------------------------------------------------------------
__global__ __launch_bounds__(256) void split_q_k(
    const float* __restrict__ q,
    __nv_bfloat16* __restrict__ qhi, __nv_bfloat16* __restrict__ qlo)
{
    const int idx = blockIdx.x * 256 + threadIdx.x;
    const float scale = rsqrtf(192.f);
    const float v = q[idx] * scale;
    __nv_bfloat16 h, l;
    splitHL(v, h, l);
    qhi[idx] = h; qlo[idx] = l;
}

__global__ __launch_bounds__(256) void split_k_k(
    const float* __restrict__ kv, const float* __restrict__ kpe,
    __nv_bfloat16* __restrict__ khi, __nv_bfloat16* __restrict__ klo)
{
    const int idx = blockIdx.x * 256 + threadIdx.x;
    const int t = idx / QROW;
    const int j = idx % QROW;
    const int h = j / QHD;
    const int d = j % QHD;
    const float v = (d < DNOPE)
        ? kv[(size_t)t * KVROW + h * 256 + d]
        : kpe[(size_t)t * DROPE + (d - DNOPE)];
    __nv_bfloat16 hi, lo;
    splitHL(v, hi, lo);
    khi[idx] = hi; klo[idx] = lo;
}

__global__ __launch_bounds__(256) void split_vt_k(
    const float* __restrict__ kv,
    __nv_bfloat16* __restrict__ vthi, __nv_bfloat16* __restrict__ vtlo)
{
    __shared__ float tile[64][65];
    const int tb = blockIdx.x;
    const int nb = blockIdx.y;
    const int h  = blockIdx.z;
    const int tid = threadIdx.x;
#pragma unroll
    for (int i = 0; i < 16; i++) {
        const int lin = i * 256 + tid;
        const int t = lin >> 6, n = lin & 63;
        tile[t][n] = kv[(size_t)(tb*64 + t) * KVROW + h*256 + DNOPE + nb*64 + n];
    }
    __syncthreads();
#pragma unroll
    for (int i = 0; i < 16; i++) {
        const int lin = i * 256 + tid;
        const int n = lin >> 6, t = lin & 63;
        __nv_bfloat16 hi, lo;
        splitHL(tile[t][n], hi, lo);
        const size_t dst = (size_t)(h*DVDIM + nb*64 + n) * SEQ + tb*64 + t;
        vthi[dst] = hi; vtlo[dst] = lo;
    }
}

// ---------------------------------------------------------------------------
// Tensor-core flash attention (bf16 hi/lo 3-pass, ldmatrix) with V chunk-0
// prefetch overlapping the softmax section.
// ---------------------------------------------------------------------------
#define QPS 200
#define KPS 72
#define VPS 72
#define PPS 72

#define OB_QHI 0
#define OB_QLO (OB_QHI + 64*QPS*2)
#define OB_KHI (OB_QLO + 64*QPS*2)
#define OB_KLO (OB_KHI + 64*KPS*2)
#define OB_VHI (OB_KLO + 64*KPS*2)
#define OB_VLO (OB_VHI + 64*VPS*2)
#define OB_PHI (OB_VLO + 64*VPS*2)
#define OB_PLO (OB_PHI + 64*PPS*2)
#define OB_ST  (OB_PLO + 64*PPS*2)
#define ATTN_SMEM (OB_ST + 704*4)

__device__ __forceinline__ void mma16(float* d,
    uint32_t a0, uint32_t a1, uint32_t a2, uint32_t a3,
    uint32_t b0, uint32_t b1)
{
    asm volatile(
        "mma.sync.aligned.m16n8k16.row.col.f32.bf16.bf16.f32 "
        "{%0,%1,%2,%3}, {%4,%5,%6,%7}, {%8,%9}, {%0,%1,%2,%3};\n"
        : "+f"(d[0]), "+f"(d[1]), "+f"(d[2]), "+f"(d[3])
        : "r"(a0), "r"(a1), "r"(a2), "r"(a3), "r"(b0), "r"(b1));
}

__device__ __forceinline__ void ldm4(uint32_t* r, uint32_t a) {
    asm volatile("ldmatrix.sync.aligned.m8n8.x4.shared.b16 {%0,%1,%2,%3}, [%4];"
        : "=r"(r[0]), "=r"(r[1]), "=r"(r[2]), "=r"(r[3]) : "r"(a));
}
__device__ __forceinline__ void ldm2(uint32_t* r, uint32_t a) {
    asm volatile("ldmatrix.sync.aligned.m8n8.x2.shared.b16 {%0,%1}, [%2];"
        : "=r"(r[0]), "=r"(r[1]) : "r"(a));
}
__device__ __forceinline__ void cp16(uint32_t dst, const void* src) {
    asm volatile("cp.async.cg.shared.global [%0], [%1], 16;\n"
                 :: "r"(dst), "l"(src));
}

__global__ __launch_bounds__(256, 2) void mla_attn_tc(
    const __nv_bfloat16* __restrict__ qhi, const __nv_bfloat16* __restrict__ qlo,
    const __nv_bfloat16* __restrict__ khi, const __nv_bfloat16* __restrict__ klo,
    const __nv_bfloat16* __restrict__ vthi, const __nv_bfloat16* __restrict__ vtlo,
    float* __restrict__ out)
{
    extern __shared__ char smraw[];
    __nv_bfloat16* Qh = (__nv_bfloat16*)(smraw + OB_QHI);
    __nv_bfloat16* Ql = (__nv_bfloat16*)(smraw + OB_QLO);
    __nv_bfloat16* Kh = (__nv_bfloat16*)(smraw + OB_KHI);
    __nv_bfloat16* Kl = (__nv_bfloat16*)(smraw + OB_KLO);
    __nv_bfloat16* Vh = (__nv_bfloat16*)(smraw + OB_VHI);
    __nv_bfloat16* Vl = (__nv_bfloat16*)(smraw + OB_VLO);
    __nv_bfloat16* Ph = (__nv_bfloat16*)(smraw + OB_PHI);
    __nv_bfloat16* Pl = (__nv_bfloat16*)(smraw + OB_PLO);
    float* smM  = (float*)(smraw + OB_ST);
    float* smL  = smM + 64;
    float* smF  = smL + 64;
    float* redM = smF + 64;
    float* redS = redM + 256;

    const int h  = blockIdx.y;
    const int qb = gridDim.x - 1 - blockIdx.x;
    const int tid = threadIdx.x;
    const int lane = tid & 31;
    const int wid = tid >> 5;
    const int wr = wid >> 2;
    const int wc = wid & 3;
    const int lq = lane >> 2;
    const int lr = lane & 3;

    const int arow = lane & 15;
    const int acol8 = (lane >> 4) * 8;
    const int brow = lane & 7;
    const int bcol8 = ((lane >> 3) & 1) * 8;

#pragma unroll
    for (int i = 0; i < 6; i++) {
        const int lin = i * 256 + tid;
        const int r = lin / 24, s = lin % 24;
        const size_t g = (size_t)(qb*64 + r) * QROW + h*QHD + s*8;
        cp16((uint32_t)__cvta_generic_to_shared(&Qh[r*QPS + s*8]), &qhi[g]);
        cp16((uint32_t)__cvta_generic_to_shared(&Ql[r*QPS + s*8]), &qlo[g]);
    }
    asm volatile("cp.async.commit_group;\n");
    if (tid < 64) { smM[tid] = -INFINITY; smL[tid] = 0.f; }

    float Oacc[2][4][4];
#pragma unroll
    for (int mt = 0; mt < 2; mt++)
#pragma unroll
        for (int nt = 0; nt < 4; nt++)
#pragma unroll
            for (int i = 0; i < 4; i++) Oacc[mt][nt][i] = 0.f;

    for (int kb = 0; kb <= qb; kb++) {
        float Sacc[2][2][4];
#pragma unroll
        for (int mt = 0; mt < 2; mt++)
#pragma unroll
            for (int nt = 0; nt < 2; nt++)
#pragma unroll
                for (int i = 0; i < 4; i++) Sacc[mt][nt][i] = 0.f;

#pragma unroll 1
        for (int c = 0; c < 3; c++) {
            if (c) __syncthreads();
#pragma unroll
            for (int i = 0; i < 2; i++) {
                const int lin = i * 256 + tid;
                const int r = lin >> 3, s = lin & 7;
                const size_t g = (size_t)(kb*64 + r) * QROW + h*QHD + c*64 + s*8;
                cp16((uint32_t)__cvta_generic_to_shared(&Kh[r*KPS + s*8]), &khi[g]);
                cp16((uint32_t)__cvta_generic_to_shared(&Kl[r*KPS + s*8]), &klo[g]);
            }
            asm volatile("cp.async.commit_group;\n");
            asm volatile("cp.async.wait_group 0;\n");
            __syncthreads();

#pragma unroll
            for (int ks = 0; ks < 4; ks++) {
                const int kof = ks * 16;
                uint32_t bh[2][2], bl[2][2];
#pragma unroll
                for (int nt = 0; nt < 2; nt++) {
                    const int n = wc*16 + nt*8 + brow;
                    ldm2(bh[nt], (uint32_t)__cvta_generic_to_shared(
                        &Kh[n*KPS + kof + bcol8]));
                    ldm2(bl[nt], (uint32_t)__cvta_generic_to_shared(
                        &Kl[n*KPS + kof + bcol8]));
                }
#pragma unroll
                for (int mt = 0; mt < 2; mt++) {
                    const int r = wr*32 + mt*16 + arow;
                    uint32_t ah[4], al[4];
                    ldm4(ah, (uint32_t)__cvta_generic_to_shared(
                        &Qh[r*QPS + c*64 + kof + acol8]));
                    ldm4(al, (uint32_t)__cvta_generic_to_shared(
                        &Ql[r*QPS + c*64 + kof + acol8]));
#pragma unroll
                    for (int nt = 0; nt < 2; nt++) {
                        mma16(Sacc[mt][nt], ah[0], ah[1], ah[2], ah[3], bh[nt][0], bh[nt][1]);
                        mma16(Sacc[mt][nt], al[0], al[1], al[2], al[3], bh[nt][0], bh[nt][1]);
                        mma16(Sacc[mt][nt], ah[0], ah[1], ah[2], ah[3], bl[nt][0], bl[nt][1]);
                    }
                }
            }
        }

        // ---- prefetch V chunk 0 (Vh/Vl free: >=2 barriers since last PV read)
        {
#pragma unroll
            for (int i = 0; i < 2; i++) {
                const int lin = i * 256 + tid;
                const int n = lin >> 3, s = lin & 7;
                const size_t g = (size_t)(h*DVDIM + n) * SEQ + kb*64 + s*8;
                cp16((uint32_t)__cvta_generic_to_shared(&Vh[n*VPS + s*8]), &vthi[g]);
                cp16((uint32_t)__cvta_generic_to_shared(&Vl[n*VPS + s*8]), &vtlo[g]);
            }
            asm volatile("cp.async.commit_group;\n");
        }

        // ---- softmax (overlaps V chunk-0 load)
        float tmax[2][2] = { {-INFINITY,-INFINITY}, {-INFINITY,-INFINITY} };
#pragma unroll
        for (int mt = 0; mt < 2; mt++)
#pragma unroll
            for (int nt = 0; nt < 2; nt++)
#pragma unroll
                for (int i = 0; i < 4; i++) {
                    if (kb == qb) {
                        const int row = wr*32 + mt*16 + lq + (i >> 1)*8;
                        const int col = wc*16 + nt*8 + lr*2 + (i & 1);
                        if (col > row) Sacc[mt][nt][i] = -INFINITY;
                    }
                    tmax[mt][i>>1] = fmaxf(tmax[mt][i>>1], Sacc[mt][nt][i]);
                }
#pragma unroll
        for (int mt = 0; mt < 2; mt++)
#pragma unroll
            for (int u = 0; u < 2; u++) {
                float v = tmax[mt][u];
                v = fmaxf(v, __shfl_xor_sync(0xffffffffu, v, 1));
                v = fmaxf(v, __shfl_xor_sync(0xffffffffu, v, 2));
                tmax[mt][u] = v;
            }
        if (lr == 0) {
#pragma unroll
            for (int mt = 0; mt < 2; mt++)
#pragma unroll
                for (int u = 0; u < 2; u++)
                    redM[(wr*32 + mt*16 + lq + u*8)*4 + wc] = tmax[mt][u];
        }
        __syncthreads();

        if (wc == 0 && lr == 0) {
#pragma unroll
            for (int mt = 0; mt < 2; mt++)
#pragma unroll
                for (int u = 0; u < 2; u++) {
                    const int row = wr*32 + mt*16 + lq + u*8;
                    float mx = fmaxf(fmaxf(redM[row*4+0], redM[row*4+1]),
                                     fmaxf(redM[row*4+2], redM[row*4+3]));
                    const float mo = smM[row];
                    const float mn = fmaxf(mo, mx);
                    smM[row] = mn;
                    smF[row] = __expf(mo - mn);
                }
        }
        __syncthreads();

        float mn[2][2];
#pragma unroll
        for (int mt = 0; mt < 2; mt++)
#pragma unroll
            for (int u = 0; u < 2; u++)
                mn[mt][u] = smM[wr*32 + mt*16 + lq + u*8];

        float tsum[2][2] = { {0.f,0.f}, {0.f,0.f} };
#pragma unroll
        for (int mt = 0; mt < 2; mt++)
#pragma unroll
            for (int nt = 0; nt < 2; nt++)
#pragma unroll
                for (int u = 0; u < 2; u++) {
                    const float p0 = __expf(Sacc[mt][nt][u*2+0] - mn[mt][u]);
                    const float p1 = __expf(Sacc[mt][nt][u*2+1] - mn[mt][u]);
                    const int row = wr*32 + mt*16 + lq + u*8;
                    const int col = wc*16 + nt*8 + lr*2;
                    __nv_bfloat16 h0, l0, h1, l1;
                    splitHL(p0, h0, l0);
                    splitHL(p1, h1, l1);
                    *(uint32_t*)&Ph[row*PPS + col] =
                        (uint32_t)__bfloat16_as_ushort(h0)
                      | ((uint32_t)__bfloat16_as_ushort(h1) << 16);
                    *(uint32_t*)&Pl[row*PPS + col] =
                        (uint32_t)__bfloat16_as_ushort(l0)
                      | ((uint32_t)__bfloat16_as_ushort(l1) << 16);
                    tsum[mt][u] += p0 + p1;
                }
#pragma unroll
        for (int mt = 0; mt < 2; mt++)
#pragma unroll
            for (int u = 0; u < 2; u++) {
                float v = tsum[mt][u];
                v += __shfl_xor_sync(0xffffffffu, v, 1);
                v += __shfl_xor_sync(0xffffffffu, v, 2);
                tsum[mt][u] = v;
            }
        if (lr == 0) {
#pragma unroll
            for (int mt = 0; mt < 2; mt++)
#pragma unroll
                for (int u = 0; u < 2; u++)
                    redS[(wr*32 + mt*16 + lq + u*8)*4 + wc] = tsum[mt][u];
        }
#pragma unroll
        for (int mt = 0; mt < 2; mt++) {
            const int r0 = wr*32 + mt*16 + lq;
            const float f0 = smF[r0], f1 = smF[r0 + 8];
#pragma unroll
            for (int nt = 0; nt < 4; nt++) {
                Oacc[mt][nt][0] *= f0; Oacc[mt][nt][1] *= f0;
                Oacc[mt][nt][2] *= f1; Oacc[mt][nt][3] *= f1;
            }
        }
        __syncthreads();

        if (wc == 0 && lr == 0) {
#pragma unroll
            for (int mt = 0; mt < 2; mt++)
#pragma unroll
                for (int u = 0; u < 2; u++) {
                    const int row = wr*32 + mt*16 + lq + u*8;
                    smL[row] = smL[row]*smF[row] +
                        (redS[row*4+0] + redS[row*4+1] + redS[row*4+2] + redS[row*4+3]);
                }
        }

        // ---- O += P V; chunk 0 uses the prefetched tile.
#pragma unroll 1
        for (int c = 0; c < 2; c++) {
            if (c == 0) {
                asm volatile("cp.async.wait_group 0;\n");
                __syncthreads();
            } else {
                __syncthreads();
#pragma unroll
                for (int i = 0; i < 2; i++) {
                    const int lin = i * 256 + tid;
                    const int n = lin >> 3, s = lin & 7;
                    const size_t g = (size_t)(h*DVDIM + 64 + n) * SEQ + kb*64 + s*8;
                    cp16((uint32_t)__cvta_generic_to_shared(&Vh[n*VPS + s*8]), &vthi[g]);
                    cp16((uint32_t)__cvta_generic_to_shared(&Vl[n*VPS + s*8]), &vtlo[g]);
                }
                asm volatile("cp.async.commit_group;\n");
                asm volatile("cp.async.wait_group 0;\n");
                __syncthreads();
            }

#pragma unroll
            for (int ks = 0; ks < 4; ks++) {
                const int kof = ks * 16;
                uint32_t bh[2][2], bl[2][2];
#pragma unroll
                for (int ntl = 0; ntl < 2; ntl++) {
                    const int n = ntl*32 + wc*8 + brow;
                    ldm2(bh[ntl], (uint32_t)__cvta_generic_to_shared(
                        &Vh[n*VPS + kof + bcol8]));
                    ldm2(bl[ntl], (uint32_t)__cvta_generic_to_shared(
                        &Vl[n*VPS + kof + bcol8]));
                }
#pragma unroll
                for (int mt = 0; mt < 2; mt++) {
                    const int r = wr*32 + mt*16 + arow;
                    uint32_t ah[4], al[4];
                    ldm4(ah, (uint32_t)__cvta_generic_to_shared(
                        &Ph[r*PPS + kof + acol8]));
                    ldm4(al, (uint32_t)__cvta_generic_to_shared(
                        &Pl[r*PPS + kof + acol8]));
#pragma unroll
                    for (int ntl = 0; ntl < 2; ntl++) {
                        const int nt = c*2 + ntl;
                        mma16(Oacc[mt][nt], ah[0], ah[1], ah[2], ah[3], bh[ntl][0], bh[ntl][1]);
                        mma16(Oacc[mt][nt], al[0], al[1], al[2], al[3], bh[ntl][0], bh[ntl][1]);
                        mma16(Oacc[mt][nt], ah[0], ah[1], ah[2], ah[3], bl[ntl][0], bl[ntl][1]);
                    }
                }
            }
        }
    }

    __syncthreads();

#pragma unroll
    for (int mt = 0; mt < 2; mt++) {
        const int r0 = wr*32 + mt*16 + lq;
        const float inv0 = 1.f / smL[r0];
        const float inv1 = 1.f / smL[r0 + 8];
#pragma unroll
        for (int nt = 0; nt < 4; nt++) {
#pragma unroll
            for (int i = 0; i < 4; i++) {
                const int row = (i < 2) ? r0 : (r0 + 8);
                const int col = nt*32 + wc*8 + lr*2 + (i & 1);
                out[(size_t)(qb*64 + row) * HID + h*DVDIM + col] =
                    rna(Oacc[mt][nt][i] * ((i < 2) ? inv0 : inv1));
            }
        }
    }
}

// ---------------------------------------------------------------------------
// Launch
// ---------------------------------------------------------------------------
static inline void launch_tgemm(const float* A, const float* B, float* C,
                                int M, int N, int K)
{
    const int tilesX = (N + BN - 1) / BN;
    const int tiles = tilesX * (M / BM);
    const int grid = tiles < PERSIST_CTAS ? tiles : PERSIST_CTAS;
    tgemm_k<<<grid, 256, GEMM_SMEM>>>(A, B, C, M, N, K, tilesX, tiles);
}

static inline void launch_round(const float* in, float* out, int n)
{
    const int n4 = n / 4;
    round_copy_k<<<(n4 + 255) / 256, 256>>>(
        (const float4*)in, (float4*)out, n4);
}

extern "C" void kernel_launch(void* const* d_in, const int* in_sizes, int n_in,
                              void* d_out, int out_size)
{
    const float* x        = (const float*)d_in[0];
    const float* wq_a     = (const float*)d_in[1];
    const float* q_a_ln_w = (const float*)d_in[2];
    const float* wq_b     = (const float*)d_in[3];
    const float* wkv_a    = (const float*)d_in[4];
    const float* kv_a_ln_w= (const float*)d_in[5];
    const float* wkv_b    = (const float*)d_in[6];
    const float* wo       = (const float*)d_in[7];
    float* out            = (float*)d_out;

    float *qact, *qa, *qbuf, *kvn, *kpe, *kv, *attn;
    float *rx, *rwcat, *rwqb, *rwkvb, *rwo;
    __nv_bfloat16 *qhi, *qlo, *khi, *klo, *vthi, *vtlo;
    cudaGetSymbolAddress((void**)&qact,  g_qact);
    cudaGetSymbolAddress((void**)&qa,    g_qa);
    cudaGetSymbolAddress((void**)&qbuf,  g_q);
    cudaGetSymbolAddress((void**)&kvn,   g_kvn);
    cudaGetSymbolAddress((void**)&kpe,   g_kpe);
    cudaGetSymbolAddress((void**)&kv,    g_kv);
    cudaGetSymbolAddress((void**)&attn,  g_attn);
    cudaGetSymbolAddress((void**)&rx,    g_rx);
    cudaGetSymbolAddress((void**)&rwcat, g_rwcat);
    cudaGetSymbolAddress((void**)&rwqb,  g_rwqb);
    cudaGetSymbolAddress((void**)&rwkvb, g_rwkvb);
    cudaGetSymbolAddress((void**)&rwo,   g_rwo);
    cudaGetSymbolAddress((void**)&qhi,   g_qhi);
    cudaGetSymbolAddress((void**)&qlo,   g_qlo);
    cudaGetSymbolAddress((void**)&khi,   g_khi);
    cudaGetSymbolAddress((void**)&klo,   g_klo);
    cudaGetSymbolAddress((void**)&vthi,  g_vthi);
    cudaGetSymbolAddress((void**)&vtlo,  g_vtlo);

    cudaFuncSetAttribute(tgemm_k,
        cudaFuncAttributeMaxDynamicSharedMemorySize, GEMM_SMEM);
    cudaFuncSetAttribute(mla_attn_tc,
        cudaFuncAttributeMaxDynamicSharedMemorySize, ATTN_SMEM);

    // idx 0..2 preps; idx 3 = profiled fused GEMM (M=2048, N=2112, K=2048)
    launch_round(x, rx, SEQ*HID);                                        // 0
    round_strided_k<<<HID*QLORA/256, 256>>>(
        wq_a, rwcat, QLORA, CATN, 0, HID*QLORA);                         // 1
    round_strided_k<<<(HID*CKVROW + 255)/256, 256>>>(
        wkv_a, rwcat, CKVROW, CATN, QLORA, HID*CKVROW);                  // 2
    launch_tgemm(rx, rwcat, qact, SEQ, CATN, HID);                       // 3 <- profiled

    // q path
    rmsnorm_k<<<SEQ, 256>>>(qact, CATN, qa, QLORA, QLORA, q_a_ln_w);
    launch_round(wq_b, rwqb, QLORA*QROW);
    launch_tgemm(qa, rwqb, qbuf, SEQ, QROW, QLORA);

    // kv path
    rmsnorm_k<<<SEQ, 256>>>(qact + QLORA, CATN, kvn, KVLORA, KVLORA, kv_a_ln_w);
    rope_k_k<<<SEQ, 32>>>(qact, kpe);
    launch_round(wkv_b, rwkvb, KVLORA*KVROW);
    launch_tgemm(kvn, rwkvb, kv, SEQ, KVROW, KVLORA);

    // rope q, then bf16 hi/lo pre-splits
    rope_q_k<<<SEQ, 512>>>(qbuf);
    split_q_k<<<SEQ*QROW/256, 256>>>(qbuf, qhi, qlo);
    split_k_k<<<SEQ*QROW/256, 256>>>(kv, kpe, khi, klo);
    {
        dim3 g(SEQ/64, DVDIM/64, NHEADS);
        split_vt_k<<<g, 256>>>(kv, vthi, vtlo);
    }

    // attention (writes tf32-rounded output)
    dim3 agrid(SEQ / 64, NHEADS);
    mla_attn_tc<<<agrid, 256, ATTN_SMEM>>>(qhi, qlo, khi, klo, vthi, vtlo, attn);

    // output projection
    launch_round(wo, rwo, HID*HID);
    launch_tgemm(attn, rwo, out, SEQ, HID, NHEADS * DVDIM);
}